// round 5
// baseline (speedup 1.0000x reference)
#include <cuda_runtime.h>
#include <math.h>

#define SEQ  2048
#define HDIM 1024
#define GDIM 4096   // 4*H
#define NCLS 512
#define NB   128    // scan grid (<= SM count -> all resident)

typedef unsigned long long ull;

// ---------------- scratch (static device globals; zero-initialized) ----------
__device__ float g_gx[SEQ * GDIM];      // 32 MB: precomputed input gates
__device__ float g_seqA[SEQ * HDIM];    // 8 MB: layer output ping
__device__ float g_seqB[SEQ * HDIM];    // 8 MB: layer output pong
__device__ float g_Wt[HDIM * GDIM];     // 16 MB: transposed weight (max size)
__device__ float g_bzero[GDIM];         // stays zero (dummy 2nd bias)
__device__ ull   g_hseq[SEQ * HDIM];    // 16 MB: packed {h,tag} handoff

// ---------------- packed f32x2 helpers ----------------------------------------
__device__ __forceinline__ ull pk(float lo, float hi) {
    ull r; asm("mov.b64 %0, {%1, %2};" : "=l"(r) : "f"(lo), "f"(hi)); return r;
}
__device__ __forceinline__ float2 up(ull v) {
    float2 r; asm("mov.b64 {%0, %1}, %2;" : "=f"(r.x), "=f"(r.y) : "l"(v)); return r;
}
__device__ __forceinline__ void fma2(ull& d, ull a, ull b) {
    asm("fma.rn.f32x2 %0, %1, %2, %0;" : "+l"(d) : "l"(a), "l"(b));
}

// ---------------- fast, overflow-safe activations (round-4 proven) ------------
__device__ __forceinline__ float fast_sigmoid(float x) {
    return __fdividef(1.f, 1.f + __expf(-x));
}
__device__ __forceinline__ float fast_tanh(float x) {
    float ax = fabsf(x);
    float e  = __expf(2.f * ax);
    float t  = 1.f - __fdividef(2.f, e + 1.f);
    return copysignf(t, x);
}

// ---------------- transpose: Wt[c][r] = W[r][c] --------------------------------
__global__ void transpose_k(const float* __restrict__ W, float* __restrict__ Wt,
                            int R, int C) {
    __shared__ float tile[32][33];
    int c0 = blockIdx.x * 32, r0 = blockIdx.y * 32;
    int x = threadIdx.x, y = threadIdx.y;
#pragma unroll
    for (int j = 0; j < 32; j += 8)
        tile[y + j][x] = W[(size_t)(r0 + y + j) * C + (c0 + x)];
    __syncthreads();
#pragma unroll
    for (int j = 0; j < 32; j += 8)
        Wt[(size_t)(c0 + y + j) * R + (r0 + x)] = tile[x][y + j];
}

// ---------------- SGEMM (round-1/4 known-good) ---------------------------------
__global__ void __launch_bounds__(256) sgemm_bias_k(
    const float* __restrict__ A, const float* __restrict__ B,
    const float* __restrict__ b1, const float* __restrict__ b2,
    float* __restrict__ C, int M, int N, int K) {
    __shared__ float As[8][128];
    __shared__ float Bs[8][128];
    const int tid  = threadIdx.x;
    const int tx   = tid & 15;
    const int ty   = tid >> 4;
    const int brow = blockIdx.y * 128;
    const int bcol = blockIdx.x * 128;

    const int ar  = tid >> 1;
    const int ak  = (tid & 1) * 4;
    const int bkk = tid >> 5;
    const int bn  = (tid & 31) * 4;

    const float* Aptr = A + (size_t)(brow + ar) * K + ak;
    const float* Bptr = B + (size_t)bkk * N + bcol + bn;

    float acc[8][8];
#pragma unroll
    for (int i = 0; i < 8; i++)
#pragma unroll
        for (int j = 0; j < 8; j++) acc[i][j] = 0.f;

    for (int k0 = 0; k0 < K; k0 += 8) {
        float4 av = *(const float4*)(Aptr + k0);
        float4 bv = *(const float4*)(Bptr + (size_t)k0 * N);
        __syncthreads();
        As[ak + 0][ar] = av.x; As[ak + 1][ar] = av.y;
        As[ak + 2][ar] = av.z; As[ak + 3][ar] = av.w;
        *(float4*)&Bs[bkk][bn] = bv;
        __syncthreads();
#pragma unroll
        for (int kk = 0; kk < 8; kk++) {
            float a[8], b[8];
            *(float4*)&a[0] = *(const float4*)&As[kk][ty * 4];
            *(float4*)&a[4] = *(const float4*)&As[kk][64 + ty * 4];
            *(float4*)&b[0] = *(const float4*)&Bs[kk][tx * 4];
            *(float4*)&b[4] = *(const float4*)&Bs[kk][64 + tx * 4];
#pragma unroll
            for (int i = 0; i < 8; i++)
#pragma unroll
                for (int j = 0; j < 8; j++)
                    acc[i][j] = fmaf(a[i], b[j], acc[i][j]);
        }
    }
#pragma unroll
    for (int i = 0; i < 8; i++) {
        int row = brow + ((i < 4) ? (ty * 4 + i) : (64 + ty * 4 + (i - 4)));
#pragma unroll
        for (int jq = 0; jq < 2; jq++) {
            int col = bcol + ((jq == 0) ? (tx * 4) : (64 + tx * 4));
            float4 o;
            o.x = acc[i][jq * 4 + 0] + b1[col + 0] + b2[col + 0];
            o.y = acc[i][jq * 4 + 1] + b1[col + 1] + b2[col + 1];
            o.z = acc[i][jq * 4 + 2] + b1[col + 2] + b2[col + 2];
            o.w = acc[i][jq * 4 + 3] + b1[col + 3] + b2[col + 3];
            *(float4*)&C[(size_t)row * N + col] = o;
        }
    }
}

// ---------------- persistent LSTM scan (atomic b64 {h,tag} handoff) ------------
// grid = 128 CTAs x 256 threads. CTA b owns units [8b, 8b+8); warp w -> unit
// u = 8b + w. Producer publishes {h,tag} as ONE 8-byte relaxed atomic store;
// consumers poll the data itself (readiness check IS the broadcast load).
// Single-copy atomicity of b64 atomics closes the v2-store tearing hole that
// broke rounds 2/3. No fences or counters needed: payload and flag share the atom.
__global__ void __launch_bounds__(256, 1) lstm_scan_k(
    const float* __restrict__ Whh, const float* __restrict__ gx,
    float* __restrict__ seqout, ull* __restrict__ hseq, unsigned tagbase) {
    __shared__ float4 sh[HDIM / 4];
    const int tid  = threadIdx.x;
    const int lane = tid & 31;
    const int w    = tid >> 5;
    const int u    = blockIdx.x * 8 + w;

    // persistent weights in registers, packed as f32x2 pairs
    ull wp[4][16];
#pragma unroll
    for (int g = 0; g < 4; g++) {
        const float* wptr = Whh + (size_t)(g * HDIM + u) * HDIM + lane * 4;
#pragma unroll
        for (int c = 0; c < 8; c++) {
            float4 v = *(const float4*)(wptr + c * 128);
            wp[g][2 * c]     = pk(v.x, v.y);
            wp[g][2 * c + 1] = pk(v.z, v.w);
        }
    }

    const unsigned shb = (unsigned)__cvta_generic_to_shared(sh);
    float cst = 0.f;

    for (int t = 0; t < SEQ; t++) {
        // gx for this step: warp-broadcast loads on all lanes (overlap the poll)
        const float* p = gx + (size_t)t * GDIM + u;
        float gi = __ldg(p);
        float gf = __ldg(p + HDIM);
        float gg = __ldg(p + 2 * HDIM);
        float go = __ldg(p + 3 * HDIM);

        if (t == 0) {
            sh[tid] = make_float4(0.f, 0.f, 0.f, 0.f);
        } else {
            const unsigned expect = tagbase + (unsigned)t;  // written at step t-1
            const ull* q = hseq + (size_t)(t - 1) * HDIM + tid * 4;
            ull v0, v1, v2, v3;
            unsigned ok;
            do {
                asm volatile("ld.relaxed.gpu.global.b64 %0, [%1];" : "=l"(v0) : "l"(q));
                asm volatile("ld.relaxed.gpu.global.b64 %0, [%1];" : "=l"(v1) : "l"(q + 1));
                asm volatile("ld.relaxed.gpu.global.b64 %0, [%1];" : "=l"(v2) : "l"(q + 2));
                asm volatile("ld.relaxed.gpu.global.b64 %0, [%1];" : "=l"(v3) : "l"(q + 3));
                ok = (unsigned)(v0 >> 32) == expect &&
                     (unsigned)(v1 >> 32) == expect &&
                     (unsigned)(v2 >> 32) == expect &&
                     (unsigned)(v3 >> 32) == expect;
            } while (!ok);
            sh[tid] = make_float4(__uint_as_float((unsigned)v0),
                                  __uint_as_float((unsigned)v1),
                                  __uint_as_float((unsigned)v2),
                                  __uint_as_float((unsigned)v3));
        }
        __syncthreads();

        ull a0 = 0ull, a1 = 0ull, a2 = 0ull, a3 = 0ull;
#pragma unroll
        for (int c = 0; c < 8; c++) {
            ull h01, h23;
            unsigned addr = shb + (unsigned)((c * 32 + lane) * 16);
            asm volatile("ld.shared.v2.u64 {%0,%1}, [%2];" : "=l"(h01), "=l"(h23) : "r"(addr));
            fma2(a0, wp[0][2 * c], h01); fma2(a0, wp[0][2 * c + 1], h23);
            fma2(a1, wp[1][2 * c], h01); fma2(a1, wp[1][2 * c + 1], h23);
            fma2(a2, wp[2][2 * c], h01); fma2(a2, wp[2][2 * c + 1], h23);
            fma2(a3, wp[3][2 * c], h01); fma2(a3, wp[3][2 * c + 1], h23);
        }
        float2 p0 = up(a0), p1 = up(a1), p2 = up(a2), p3 = up(a3);
        float s0 = p0.x + p0.y, s1 = p1.x + p1.y;
        float s2 = p2.x + p2.y, s3 = p3.x + p3.y;
#pragma unroll
        for (int s = 16; s > 0; s >>= 1) {
            s0 += __shfl_xor_sync(0xffffffffu, s0, s);
            s1 += __shfl_xor_sync(0xffffffffu, s1, s);
            s2 += __shfl_xor_sync(0xffffffffu, s2, s);
            s3 += __shfl_xor_sync(0xffffffffu, s3, s);
        }
        // all lanes compute identical gates (no divergence, MUFU fast path)
        float iv = fast_sigmoid(s0 + gi);
        float fv = fast_sigmoid(s1 + gf);
        float gv = fast_tanh(s2 + gg);
        float ov = fast_sigmoid(s3 + go);
        cst = fmaf(fv, cst, iv * gv);
        float h = ov * fast_tanh(cst);
        if (lane == 0) {
            seqout[(size_t)t * HDIM + u] = h;
            ull pkv = ((ull)(tagbase + (unsigned)t + 1u) << 32) |
                      (ull)__float_as_uint(h);
            const ull* hp = hseq + (size_t)t * HDIM + u;
            asm volatile("st.relaxed.gpu.global.b64 [%0], %1;"
                         :: "l"(hp), "l"(pkv) : "memory");
        }
        __syncthreads();   // protect sh from next iteration's writes
    }
}

// ---------------- launch ----------------
extern "C" void kernel_launch(void* const* d_in, const int* in_sizes, int n_in,
                              void* d_out, int out_size) {
    const float* x      = (const float*)d_in[0];
    const float* Wih[3] = {(const float*)d_in[1], (const float*)d_in[5],  (const float*)d_in[9]};
    const float* Whh[3] = {(const float*)d_in[2], (const float*)d_in[6],  (const float*)d_in[10]};
    const float* bih[3] = {(const float*)d_in[3], (const float*)d_in[7],  (const float*)d_in[11]};
    const float* bhh[3] = {(const float*)d_in[4], (const float*)d_in[8],  (const float*)d_in[12]};
    const float* fcw    = (const float*)d_in[13];
    const float* fcb    = (const float*)d_in[14];
    float* out = (float*)d_out;

    float *gx, *seqA, *seqB, *Wt, *bz;
    ull* hseq;
    cudaGetSymbolAddress((void**)&gx,   g_gx);
    cudaGetSymbolAddress((void**)&seqA, g_seqA);
    cudaGetSymbolAddress((void**)&seqB, g_seqB);
    cudaGetSymbolAddress((void**)&Wt,   g_Wt);
    cudaGetSymbolAddress((void**)&bz,   g_bzero);
    cudaGetSymbolAddress((void**)&hseq, g_hseq);

    const float* ins[3]  = {x, seqA, seqB};
    float*       outs[3] = {seqA, seqB, seqA};

    dim3 tb(32, 8);
    for (int l = 0; l < 3; l++) {
        transpose_k<<<dim3(HDIM / 32, GDIM / 32), tb>>>(Wih[l], Wt, GDIM, HDIM);
        sgemm_bias_k<<<dim3(GDIM / 128, SEQ / 128), 256>>>(
            ins[l], Wt, bih[l], bhh[l], gx, SEQ, GDIM, HDIM);
        lstm_scan_k<<<NB, 256>>>(Whh[l], gx, outs[l], hseq, (unsigned)(l * SEQ));
    }
    // FC head
    transpose_k<<<dim3(HDIM / 32, NCLS / 32), tb>>>(fcw, Wt, NCLS, HDIM);
    sgemm_bias_k<<<dim3(NCLS / 128, SEQ / 128), 256>>>(
        seqA, Wt, fcb, bz, out, SEQ, NCLS, HDIM);
}

// round 6
// speedup vs baseline: 1.1140x; 1.1140x over previous
#include <cuda_runtime.h>
#include <math.h>

#define SEQ  2048
#define HDIM 1024
#define GDIM 4096   // 4*H
#define NCLS 512
#define NB   128    // scan grid (<= SM count -> all resident)

typedef unsigned long long ull;

// ---------------- scratch (static device globals; zero-initialized) ----------
__device__ float    g_gx[SEQ * GDIM];      // 32 MB: precomputed input gates
__device__ float    g_seqA[SEQ * HDIM];    // 8 MB: layer output ping
__device__ float    g_seqB[SEQ * HDIM];    // 8 MB: layer output pong
__device__ float    g_Wt[HDIM * GDIM];     // 16 MB: transposed weight (max size)
__device__ float    g_bzero[GDIM];         // stays zero (dummy 2nd bias)
__device__ unsigned g_flags[NB];           // per-CTA progress flags

// ---------------- packed f32x2 helpers (validated round 5) --------------------
__device__ __forceinline__ ull pk(float lo, float hi) {
    ull r; asm("mov.b64 %0, {%1, %2};" : "=l"(r) : "f"(lo), "f"(hi)); return r;
}
__device__ __forceinline__ float2 up(ull v) {
    float2 r; asm("mov.b64 {%0, %1}, %2;" : "=f"(r.x), "=f"(r.y) : "l"(v)); return r;
}
__device__ __forceinline__ void fma2(ull& d, ull a, ull b) {
    asm("fma.rn.f32x2 %0, %1, %2, %0;" : "+l"(d) : "l"(a), "l"(b));
}

// ---------------- fast, overflow-safe activations (validated) -----------------
__device__ __forceinline__ float fast_sigmoid(float x) {
    return __fdividef(1.f, 1.f + __expf(-x));
}
__device__ __forceinline__ float fast_tanh(float x) {
    float ax = fabsf(x);
    float e  = __expf(2.f * ax);
    float t  = 1.f - __fdividef(2.f, e + 1.f);
    return copysignf(t, x);
}

// ---------------- transpose: Wt[c][r] = W[r][c] --------------------------------
__global__ void transpose_k(const float* __restrict__ W, float* __restrict__ Wt,
                            int R, int C) {
    __shared__ float tile[32][33];
    int c0 = blockIdx.x * 32, r0 = blockIdx.y * 32;
    int x = threadIdx.x, y = threadIdx.y;
#pragma unroll
    for (int j = 0; j < 32; j += 8)
        tile[y + j][x] = W[(size_t)(r0 + y + j) * C + (c0 + x)];
    __syncthreads();
#pragma unroll
    for (int j = 0; j < 32; j += 8)
        Wt[(size_t)(c0 + y + j) * R + (r0 + x)] = tile[x][y + j];
}

// ---------------- zero flags ---------------------------------------------------
__global__ void zero_flags_k(unsigned* p) {
    p[threadIdx.x] = 0u;
}

// ---------------- SGEMM (round-1/4 known-good) ---------------------------------
__global__ void __launch_bounds__(256) sgemm_bias_k(
    const float* __restrict__ A, const float* __restrict__ B,
    const float* __restrict__ b1, const float* __restrict__ b2,
    float* __restrict__ C, int M, int N, int K) {
    __shared__ float As[8][128];
    __shared__ float Bs[8][128];
    const int tid  = threadIdx.x;
    const int tx   = tid & 15;
    const int ty   = tid >> 4;
    const int brow = blockIdx.y * 128;
    const int bcol = blockIdx.x * 128;

    const int ar  = tid >> 1;
    const int ak  = (tid & 1) * 4;
    const int bkk = tid >> 5;
    const int bn  = (tid & 31) * 4;

    const float* Aptr = A + (size_t)(brow + ar) * K + ak;
    const float* Bptr = B + (size_t)bkk * N + bcol + bn;

    float acc[8][8];
#pragma unroll
    for (int i = 0; i < 8; i++)
#pragma unroll
        for (int j = 0; j < 8; j++) acc[i][j] = 0.f;

    for (int k0 = 0; k0 < K; k0 += 8) {
        float4 av = *(const float4*)(Aptr + k0);
        float4 bv = *(const float4*)(Bptr + (size_t)k0 * N);
        __syncthreads();
        As[ak + 0][ar] = av.x; As[ak + 1][ar] = av.y;
        As[ak + 2][ar] = av.z; As[ak + 3][ar] = av.w;
        *(float4*)&Bs[bkk][bn] = bv;
        __syncthreads();
#pragma unroll
        for (int kk = 0; kk < 8; kk++) {
            float a[8], b[8];
            *(float4*)&a[0] = *(const float4*)&As[kk][ty * 4];
            *(float4*)&a[4] = *(const float4*)&As[kk][64 + ty * 4];
            *(float4*)&b[0] = *(const float4*)&Bs[kk][tx * 4];
            *(float4*)&b[4] = *(const float4*)&Bs[kk][64 + tx * 4];
#pragma unroll
            for (int i = 0; i < 8; i++)
#pragma unroll
                for (int j = 0; j < 8; j++)
                    acc[i][j] = fmaf(a[i], b[j], acc[i][j]);
        }
    }
#pragma unroll
    for (int i = 0; i < 8; i++) {
        int row = brow + ((i < 4) ? (ty * 4 + i) : (64 + ty * 4 + (i - 4)));
#pragma unroll
        for (int jq = 0; jq < 2; jq++) {
            int col = bcol + ((jq == 0) ? (tx * 4) : (64 + tx * 4));
            float4 o;
            o.x = acc[i][jq * 4 + 0] + b1[col + 0] + b2[col + 0];
            o.y = acc[i][jq * 4 + 1] + b1[col + 1] + b2[col + 1];
            o.z = acc[i][jq * 4 + 2] + b1[col + 2] + b2[col + 2];
            o.w = acc[i][jq * 4 + 3] + b1[col + 3] + b2[col + 3];
            *(float4*)&C[(size_t)row * N + col] = o;
        }
    }
}

// ---------------- persistent LSTM scan (per-CTA flag barrier) ------------------
// grid = 128 CTAs x 256 threads. CTA b owns units [8b, 8b+8); warp w -> unit
// u = 8b + w. Producer: h stores -> bar -> tid0 st.release.gpu flags[b]=t+1.
// Consumer: warp 0 acquire-polls all 128 flags in parallel (4/lane + ballot),
// bar, then all threads __ldcg h. Low-traffic: only 32 threads/CTA poll 512B.
__global__ void __launch_bounds__(256, 1) lstm_scan_k(
    const float* __restrict__ Whh, const float* __restrict__ gx,
    float* __restrict__ seqout, unsigned* __restrict__ flags) {
    __shared__ float4 sh[HDIM / 4];
    const int tid  = threadIdx.x;
    const int lane = tid & 31;
    const int w    = tid >> 5;
    const int u    = blockIdx.x * 8 + w;

    // persistent weights in registers, packed as f32x2 pairs
    ull wp[4][16];
#pragma unroll
    for (int g = 0; g < 4; g++) {
        const float* wptr = Whh + (size_t)(g * HDIM + u) * HDIM + lane * 4;
#pragma unroll
        for (int c = 0; c < 8; c++) {
            float4 v = *(const float4*)(wptr + c * 128);
            wp[g][2 * c]     = pk(v.x, v.y);
            wp[g][2 * c + 1] = pk(v.z, v.w);
        }
    }

    const unsigned shb = (unsigned)__cvta_generic_to_shared(sh);
    float cst = 0.f;
    const float4* hsrc = 0;

    for (int t = 0; t < SEQ; t++) {
        // gx loads for this step: warp-broadcast on all lanes
        const float* p = gx + (size_t)t * GDIM + u;
        float gi = __ldg(p);
        float gf = __ldg(p + HDIM);
        float gg = __ldg(p + 2 * HDIM);
        float go = __ldg(p + 3 * HDIM);

        if (t == 0) {
            sh[tid] = make_float4(0.f, 0.f, 0.f, 0.f);
            __syncthreads();
        } else {
            // warp 0 waits for all producers of step t-1 (flag >= t)
            if (w == 0) {
                const unsigned target = (unsigned)t;
                unsigned f0, f1, f2, f3;
                bool ok;
                do {
                    asm volatile("ld.acquire.gpu.global.u32 %0, [%1];"
                                 : "=r"(f0) : "l"(flags + lane) : "memory");
                    asm volatile("ld.acquire.gpu.global.u32 %0, [%1];"
                                 : "=r"(f1) : "l"(flags + lane + 32) : "memory");
                    asm volatile("ld.acquire.gpu.global.u32 %0, [%1];"
                                 : "=r"(f2) : "l"(flags + lane + 64) : "memory");
                    asm volatile("ld.acquire.gpu.global.u32 %0, [%1];"
                                 : "=r"(f3) : "l"(flags + lane + 96) : "memory");
                    ok = (f0 >= target) && (f1 >= target) &&
                         (f2 >= target) && (f3 >= target);
                } while (!__all_sync(0xffffffffu, ok));
            }
            __syncthreads();                    // propagate acquire block-wide
            sh[tid] = __ldcg(hsrc + tid);       // stage h_{t-1} (4KB, L2)
            __syncthreads();
        }

        ull a0 = 0ull, a1 = 0ull, a2 = 0ull, a3 = 0ull;
#pragma unroll
        for (int c = 0; c < 8; c++) {
            ull h01, h23;
            unsigned addr = shb + (unsigned)((c * 32 + lane) * 16);
            asm volatile("ld.shared.v2.u64 {%0,%1}, [%2];" : "=l"(h01), "=l"(h23) : "r"(addr));
            fma2(a0, wp[0][2 * c], h01); fma2(a0, wp[0][2 * c + 1], h23);
            fma2(a1, wp[1][2 * c], h01); fma2(a1, wp[1][2 * c + 1], h23);
            fma2(a2, wp[2][2 * c], h01); fma2(a2, wp[2][2 * c + 1], h23);
            fma2(a3, wp[3][2 * c], h01); fma2(a3, wp[3][2 * c + 1], h23);
        }
        float2 p0 = up(a0), p1 = up(a1), p2 = up(a2), p3 = up(a3);
        float s0 = p0.x + p0.y, s1 = p1.x + p1.y;
        float s2 = p2.x + p2.y, s3 = p3.x + p3.y;
#pragma unroll
        for (int s = 16; s > 0; s >>= 1) {
            s0 += __shfl_xor_sync(0xffffffffu, s0, s);
            s1 += __shfl_xor_sync(0xffffffffu, s1, s);
            s2 += __shfl_xor_sync(0xffffffffu, s2, s);
            s3 += __shfl_xor_sync(0xffffffffu, s3, s);
        }
        // all lanes compute identical gates (no divergence, MUFU fast path)
        float iv = fast_sigmoid(s0 + gi);
        float fv = fast_sigmoid(s1 + gf);
        float gv = fast_tanh(s2 + gg);
        float ov = fast_sigmoid(s3 + go);
        cst = fmaf(fv, cst, iv * gv);
        float h = ov * fast_tanh(cst);
        if (lane == 0) seqout[(size_t)t * HDIM + u] = h;

        __syncthreads();   // all 8 unit stores of this CTA done (cta fence)
        if (tid == 0) {
            asm volatile("st.release.gpu.global.u32 [%0], %1;"
                         :: "l"(flags + blockIdx.x), "r"((unsigned)(t + 1))
                         : "memory");
        }
        hsrc = (const float4*)(seqout + (size_t)t * HDIM);
        // no trailing bar: sh is rewritten only after next step's poll+bar
    }
}

// ---------------- launch ----------------
extern "C" void kernel_launch(void* const* d_in, const int* in_sizes, int n_in,
                              void* d_out, int out_size) {
    const float* x      = (const float*)d_in[0];
    const float* Wih[3] = {(const float*)d_in[1], (const float*)d_in[5],  (const float*)d_in[9]};
    const float* Whh[3] = {(const float*)d_in[2], (const float*)d_in[6],  (const float*)d_in[10]};
    const float* bih[3] = {(const float*)d_in[3], (const float*)d_in[7],  (const float*)d_in[11]};
    const float* bhh[3] = {(const float*)d_in[4], (const float*)d_in[8],  (const float*)d_in[12]};
    const float* fcw    = (const float*)d_in[13];
    const float* fcb    = (const float*)d_in[14];
    float* out = (float*)d_out;

    float *gx, *seqA, *seqB, *Wt, *bz;
    unsigned* flags;
    cudaGetSymbolAddress((void**)&gx,    g_gx);
    cudaGetSymbolAddress((void**)&seqA,  g_seqA);
    cudaGetSymbolAddress((void**)&seqB,  g_seqB);
    cudaGetSymbolAddress((void**)&Wt,    g_Wt);
    cudaGetSymbolAddress((void**)&bz,    g_bzero);
    cudaGetSymbolAddress((void**)&flags, g_flags);

    const float* ins[3]  = {x, seqA, seqB};
    float*       outs[3] = {seqA, seqB, seqA};

    dim3 tb(32, 8);
    for (int l = 0; l < 3; l++) {
        transpose_k<<<dim3(HDIM / 32, GDIM / 32), tb>>>(Wih[l], Wt, GDIM, HDIM);
        sgemm_bias_k<<<dim3(GDIM / 128, SEQ / 128), 256>>>(
            ins[l], Wt, bih[l], bhh[l], gx, SEQ, GDIM, HDIM);
        zero_flags_k<<<1, NB>>>(flags);
        lstm_scan_k<<<NB, 256>>>(Whh[l], gx, outs[l], flags);
    }
    // FC head
    transpose_k<<<dim3(HDIM / 32, NCLS / 32), tb>>>(fcw, Wt, NCLS, HDIM);
    sgemm_bias_k<<<dim3(NCLS / 128, SEQ / 128), 256>>>(
        seqA, Wt, fcb, bz, out, SEQ, NCLS, HDIM);
}

// round 7
// speedup vs baseline: 1.3458x; 1.2080x over previous
#include <cuda_runtime.h>
#include <math.h>

#define SEQ  2048
#define HDIM 1024
#define GDIM 4096   // 4*H
#define NCLS 512
#define NB   128    // scan grid (<= SM count -> all resident)
#define NGRP 8      // spread arrival counters

typedef unsigned long long ull;

// ---------------- scratch (static device globals) ------------------------------
__device__ float    g_gx[SEQ * GDIM];      // 32 MB: precomputed input gates
__device__ float    g_seqA[SEQ * HDIM];    // 8 MB: layer output ping
__device__ float    g_seqB[SEQ * HDIM];    // 8 MB: layer output pong
__device__ float    g_Wt[HDIM * GDIM];     // 16 MB: transposed weight (max size)
__device__ float    g_bzero[GDIM];         // stays zero (dummy 2nd bias)
__device__ unsigned g_cnt[NGRP * SEQ];     // counter[g*SEQ + t]: 8KB group stride

// ---------------- packed f32x2 helpers ------------------------------------------
__device__ __forceinline__ ull pk(float lo, float hi) {
    ull r; asm("mov.b64 %0, {%1, %2};" : "=l"(r) : "f"(lo), "f"(hi)); return r;
}
__device__ __forceinline__ float2 up(ull v) {
    float2 r; asm("mov.b64 {%0, %1}, %2;" : "=f"(r.x), "=f"(r.y) : "l"(v)); return r;
}
__device__ __forceinline__ void fma2(ull& d, ull a, ull b) {
    asm("fma.rn.f32x2 %0, %1, %2, %0;" : "+l"(d) : "l"(a), "l"(b));
}

// ---------------- fast, overflow-safe activations (validated) -------------------
__device__ __forceinline__ float fast_sigmoid(float x) {
    return __fdividef(1.f, 1.f + __expf(-x));
}
__device__ __forceinline__ float fast_tanh(float x) {
    float ax = fabsf(x);
    float e  = __expf(2.f * ax);
    float t  = 1.f - __fdividef(2.f, e + 1.f);
    return copysignf(t, x);
}

// ---------------- transpose: Wt[c][r] = W[r][c] ----------------------------------
__global__ void transpose_k(const float* __restrict__ W, float* __restrict__ Wt,
                            int R, int C) {
    __shared__ float tile[32][33];
    int c0 = blockIdx.x * 32, r0 = blockIdx.y * 32;
    int x = threadIdx.x, y = threadIdx.y;
#pragma unroll
    for (int j = 0; j < 32; j += 8)
        tile[y + j][x] = W[(size_t)(r0 + y + j) * C + (c0 + x)];
    __syncthreads();
#pragma unroll
    for (int j = 0; j < 32; j += 8)
        Wt[(size_t)(c0 + y + j) * R + (r0 + x)] = tile[x][y + j];
}

// ---------------- zero counters ---------------------------------------------------
__global__ void zero_k(unsigned* p, int n) {
    int i = blockIdx.x * 256 + threadIdx.x;
    if (i < n) p[i] = 0;
}

// ---------------- SGEMM (round-1/4 known-good) ------------------------------------
__global__ void __launch_bounds__(256) sgemm_bias_k(
    const float* __restrict__ A, const float* __restrict__ B,
    const float* __restrict__ b1, const float* __restrict__ b2,
    float* __restrict__ C, int M, int N, int K) {
    __shared__ float As[8][128];
    __shared__ float Bs[8][128];
    const int tid  = threadIdx.x;
    const int tx   = tid & 15;
    const int ty   = tid >> 4;
    const int brow = blockIdx.y * 128;
    const int bcol = blockIdx.x * 128;

    const int ar  = tid >> 1;
    const int ak  = (tid & 1) * 4;
    const int bkk = tid >> 5;
    const int bn  = (tid & 31) * 4;

    const float* Aptr = A + (size_t)(brow + ar) * K + ak;
    const float* Bptr = B + (size_t)bkk * N + bcol + bn;

    float acc[8][8];
#pragma unroll
    for (int i = 0; i < 8; i++)
#pragma unroll
        for (int j = 0; j < 8; j++) acc[i][j] = 0.f;

    for (int k0 = 0; k0 < K; k0 += 8) {
        float4 av = *(const float4*)(Aptr + k0);
        float4 bv = *(const float4*)(Bptr + (size_t)k0 * N);
        __syncthreads();
        As[ak + 0][ar] = av.x; As[ak + 1][ar] = av.y;
        As[ak + 2][ar] = av.z; As[ak + 3][ar] = av.w;
        *(float4*)&Bs[bkk][bn] = bv;
        __syncthreads();
#pragma unroll
        for (int kk = 0; kk < 8; kk++) {
            float a[8], b[8];
            *(float4*)&a[0] = *(const float4*)&As[kk][ty * 4];
            *(float4*)&a[4] = *(const float4*)&As[kk][64 + ty * 4];
            *(float4*)&b[0] = *(const float4*)&Bs[kk][tx * 4];
            *(float4*)&b[4] = *(const float4*)&Bs[kk][64 + tx * 4];
#pragma unroll
            for (int i = 0; i < 8; i++)
#pragma unroll
                for (int j = 0; j < 8; j++)
                    acc[i][j] = fmaf(a[i], b[j], acc[i][j]);
        }
    }
#pragma unroll
    for (int i = 0; i < 8; i++) {
        int row = brow + ((i < 4) ? (ty * 4 + i) : (64 + ty * 4 + (i - 4)));
#pragma unroll
        for (int jq = 0; jq < 2; jq++) {
            int col = bcol + ((jq == 0) ? (tx * 4) : (64 + tx * 4));
            float4 o;
            o.x = acc[i][jq * 4 + 0] + b1[col + 0] + b2[col + 0];
            o.y = acc[i][jq * 4 + 1] + b1[col + 1] + b2[col + 1];
            o.z = acc[i][jq * 4 + 2] + b1[col + 2] + b2[col + 2];
            o.w = acc[i][jq * 4 + 3] + b1[col + 3] + b2[col + 3];
            *(float4*)&C[(size_t)row * N + col] = o;
        }
    }
}

// ---------------- persistent LSTM scan (8-way spread counter barrier) -------------
// grid = 128 CTAs x 256 threads. CTA b owns units [8b, 8b+8); warp w -> unit
// u = 8b + w. Arrival: after a CTA's 8 h stores + bar, tid0 red.release's
// counter[(b&7)][t] (16 arrivals per counter, 8 L2 lines in parallel).
// Observe: warp 0 lanes 0-7 acquire-poll one counter each until ==16.
__global__ void __launch_bounds__(256, 1) lstm_scan_k(
    const float* __restrict__ Whh, const float* __restrict__ gx,
    float* __restrict__ seqout, unsigned* __restrict__ cnt) {
    __shared__ float4 sh[HDIM / 4];
    const int tid  = threadIdx.x;
    const int lane = tid & 31;
    const int w    = tid >> 5;
    const int u    = blockIdx.x * 8 + w;
    const int grp  = blockIdx.x & 7;

    // persistent weights in registers, packed as f32x2 pairs
    ull wp[4][16];
#pragma unroll
    for (int g = 0; g < 4; g++) {
        const float* wptr = Whh + (size_t)(g * HDIM + u) * HDIM + lane * 4;
#pragma unroll
        for (int c = 0; c < 8; c++) {
            float4 v = *(const float4*)(wptr + c * 128);
            wp[g][2 * c]     = pk(v.x, v.y);
            wp[g][2 * c + 1] = pk(v.z, v.w);
        }
    }

    const unsigned shb = (unsigned)__cvta_generic_to_shared(sh);
    float cst = 0.f;
    const float4* hsrc = 0;

    // prefetch gx for step 0
    float gi = __ldg(gx + u);
    float gf = __ldg(gx + HDIM + u);
    float gg = __ldg(gx + 2 * HDIM + u);
    float go = __ldg(gx + 3 * HDIM + u);

    for (int t = 0; t < SEQ; t++) {
        if (t == 0) {
            sh[tid] = make_float4(0.f, 0.f, 0.f, 0.f);
            __syncthreads();
        } else {
            // observe: warp 0, lanes 0-7 poll spread counters for step t-1
            if (w == 0) {
                bool ok = true;
                if (lane < NGRP) {
                    const unsigned* cp = cnt + lane * SEQ + (t - 1);
                    unsigned v;
                    do {
                        asm volatile("ld.acquire.gpu.global.u32 %0, [%1];"
                                     : "=r"(v) : "l"(cp) : "memory");
                    } while (v < (unsigned)(NB / NGRP));
                }
                __syncwarp();
            }
            __syncthreads();                  // propagate observation block-wide
            sh[tid] = __ldcg(hsrc + tid);     // stage h_{t-1} (4KB via L2)
            __syncthreads();
        }

        // prefetch gx for step t+1 (overlaps matvec; DRAM latency hidden)
        float ngi = 0.f, ngf = 0.f, ngg = 0.f, ngo = 0.f;
        if (t + 1 < SEQ) {
            const float* p = gx + (size_t)(t + 1) * GDIM + u;
            ngi = __ldg(p);
            ngf = __ldg(p + HDIM);
            ngg = __ldg(p + 2 * HDIM);
            ngo = __ldg(p + 3 * HDIM);
        }

        ull a0 = 0ull, a1 = 0ull, a2 = 0ull, a3 = 0ull;
#pragma unroll
        for (int c = 0; c < 8; c++) {
            ull h01, h23;
            unsigned addr = shb + (unsigned)((c * 32 + lane) * 16);
            asm volatile("ld.shared.v2.u64 {%0,%1}, [%2];" : "=l"(h01), "=l"(h23) : "r"(addr));
            fma2(a0, wp[0][2 * c], h01); fma2(a0, wp[0][2 * c + 1], h23);
            fma2(a1, wp[1][2 * c], h01); fma2(a1, wp[1][2 * c + 1], h23);
            fma2(a2, wp[2][2 * c], h01); fma2(a2, wp[2][2 * c + 1], h23);
            fma2(a3, wp[3][2 * c], h01); fma2(a3, wp[3][2 * c + 1], h23);
        }
        float2 p0 = up(a0), p1 = up(a1), p2 = up(a2), p3 = up(a3);
        float s0 = p0.x + p0.y, s1 = p1.x + p1.y;
        float s2 = p2.x + p2.y, s3 = p3.x + p3.y;
#pragma unroll
        for (int s = 16; s > 0; s >>= 1) {
            s0 += __shfl_xor_sync(0xffffffffu, s0, s);
            s1 += __shfl_xor_sync(0xffffffffu, s1, s);
            s2 += __shfl_xor_sync(0xffffffffu, s2, s);
            s3 += __shfl_xor_sync(0xffffffffu, s3, s);
        }
        // all lanes compute identical gates (no divergence, MUFU fast path)
        float iv = fast_sigmoid(s0 + gi);
        float fv = fast_sigmoid(s1 + gf);
        float gv = fast_tanh(s2 + gg);
        float ov = fast_sigmoid(s3 + go);
        cst = fmaf(fv, cst, iv * gv);
        float h = ov * fast_tanh(cst);
        if (lane == 0) seqout[(size_t)t * HDIM + u] = h;

        __syncthreads();   // all 8 unit stores of this CTA visible (cta order)
        if (tid == 0) {
            asm volatile("red.release.gpu.global.add.u32 [%0], 1;"
                         :: "l"(cnt + grp * SEQ + t) : "memory");
        }
        hsrc = (const float4*)(seqout + (size_t)t * HDIM);
        gi = ngi; gf = ngf; gg = ngg; go = ngo;
    }
}

// ---------------- launch ----------------
extern "C" void kernel_launch(void* const* d_in, const int* in_sizes, int n_in,
                              void* d_out, int out_size) {
    const float* x      = (const float*)d_in[0];
    const float* Wih[3] = {(const float*)d_in[1], (const float*)d_in[5],  (const float*)d_in[9]};
    const float* Whh[3] = {(const float*)d_in[2], (const float*)d_in[6],  (const float*)d_in[10]};
    const float* bih[3] = {(const float*)d_in[3], (const float*)d_in[7],  (const float*)d_in[11]};
    const float* bhh[3] = {(const float*)d_in[4], (const float*)d_in[8],  (const float*)d_in[12]};
    const float* fcw    = (const float*)d_in[13];
    const float* fcb    = (const float*)d_in[14];
    float* out = (float*)d_out;

    float *gx, *seqA, *seqB, *Wt, *bz;
    unsigned* cnt;
    cudaGetSymbolAddress((void**)&gx,   g_gx);
    cudaGetSymbolAddress((void**)&seqA, g_seqA);
    cudaGetSymbolAddress((void**)&seqB, g_seqB);
    cudaGetSymbolAddress((void**)&Wt,   g_Wt);
    cudaGetSymbolAddress((void**)&bz,   g_bzero);
    cudaGetSymbolAddress((void**)&cnt,  g_cnt);

    const float* ins[3]  = {x, seqA, seqB};
    float*       outs[3] = {seqA, seqB, seqA};

    dim3 tb(32, 8);
    for (int l = 0; l < 3; l++) {
        transpose_k<<<dim3(HDIM / 32, GDIM / 32), tb>>>(Wih[l], Wt, GDIM, HDIM);
        sgemm_bias_k<<<dim3(GDIM / 128, SEQ / 128), 256>>>(
            ins[l], Wt, bih[l], bhh[l], gx, SEQ, GDIM, HDIM);
        zero_k<<<(NGRP * SEQ + 255) / 256, 256>>>(cnt, NGRP * SEQ);
        lstm_scan_k<<<NB, 256>>>(Whh[l], gx, outs[l], cnt);
    }
    // FC head
    transpose_k<<<dim3(HDIM / 32, NCLS / 32), tb>>>(fcw, Wt, NCLS, HDIM);
    sgemm_bias_k<<<dim3(NCLS / 128, SEQ / 128), 256>>>(
        seqA, Wt, fcb, bz, out, SEQ, NCLS, HDIM);
}

// round 8
// speedup vs baseline: 1.5401x; 1.1444x over previous
#include <cuda_runtime.h>
#include <math.h>

#define SEQ  2048
#define HDIM 1024
#define GDIM 4096   // 4*H
#define NCLS 512
#define NB   128    // scan grid (<= SM count -> all resident)
#define NGRP 8      // warp-group arrival counters

// ---------------- scratch (static device globals) ------------------------------
__device__ float    g_gx[SEQ * GDIM];      // 32 MB: precomputed input gates
__device__ float    g_seqA[SEQ * HDIM];    // 8 MB: layer output ping
__device__ float    g_seqB[SEQ * HDIM];    // 8 MB: layer output pong
__device__ float    g_Wt[HDIM * GDIM];     // 16 MB: transposed weight (max size)
__device__ float    g_bzero[GDIM];         // stays zero (dummy 2nd bias)
__device__ unsigned g_cnt[NGRP * SEQ];     // cnt[w*SEQ + t]: 8KB group stride

// ---------------- fast, overflow-safe activations (validated r4) ----------------
__device__ __forceinline__ float fast_sigmoid(float x) {
    return __fdividef(1.f, 1.f + __expf(-x));
}
__device__ __forceinline__ float fast_tanh(float x) {
    float ax = fabsf(x);
    float e  = __expf(2.f * ax);
    float t  = 1.f - __fdividef(2.f, e + 1.f);
    return copysignf(t, x);
}

// ---------------- transpose: Wt[c][r] = W[r][c] ----------------------------------
__global__ void transpose_k(const float* __restrict__ W, float* __restrict__ Wt,
                            int R, int C) {
    __shared__ float tile[32][33];
    int c0 = blockIdx.x * 32, r0 = blockIdx.y * 32;
    int x = threadIdx.x, y = threadIdx.y;
#pragma unroll
    for (int j = 0; j < 32; j += 8)
        tile[y + j][x] = W[(size_t)(r0 + y + j) * C + (c0 + x)];
    __syncthreads();
#pragma unroll
    for (int j = 0; j < 32; j += 8)
        Wt[(size_t)(c0 + y + j) * R + (r0 + x)] = tile[x][y + j];
}

// ---------------- zero counters ----------------------------------------------------
__global__ void zero_k(unsigned* p, int n) {
    int i = blockIdx.x * 256 + threadIdx.x;
    if (i < n) p[i] = 0;
}

// ---------------- SGEMM (round-1/4 known-good) --------------------------------------
__global__ void __launch_bounds__(256) sgemm_bias_k(
    const float* __restrict__ A, const float* __restrict__ B,
    const float* __restrict__ b1, const float* __restrict__ b2,
    float* __restrict__ C, int M, int N, int K) {
    __shared__ float As[8][128];
    __shared__ float Bs[8][128];
    const int tid  = threadIdx.x;
    const int tx   = tid & 15;
    const int ty   = tid >> 4;
    const int brow = blockIdx.y * 128;
    const int bcol = blockIdx.x * 128;

    const int ar  = tid >> 1;
    const int ak  = (tid & 1) * 4;
    const int bkk = tid >> 5;
    const int bn  = (tid & 31) * 4;

    const float* Aptr = A + (size_t)(brow + ar) * K + ak;
    const float* Bptr = B + (size_t)bkk * N + bcol + bn;

    float acc[8][8];
#pragma unroll
    for (int i = 0; i < 8; i++)
#pragma unroll
        for (int j = 0; j < 8; j++) acc[i][j] = 0.f;

    for (int k0 = 0; k0 < K; k0 += 8) {
        float4 av = *(const float4*)(Aptr + k0);
        float4 bv = *(const float4*)(Bptr + (size_t)k0 * N);
        __syncthreads();
        As[ak + 0][ar] = av.x; As[ak + 1][ar] = av.y;
        As[ak + 2][ar] = av.z; As[ak + 3][ar] = av.w;
        *(float4*)&Bs[bkk][bn] = bv;
        __syncthreads();
#pragma unroll
        for (int kk = 0; kk < 8; kk++) {
            float a[8], b[8];
            *(float4*)&a[0] = *(const float4*)&As[kk][ty * 4];
            *(float4*)&a[4] = *(const float4*)&As[kk][64 + ty * 4];
            *(float4*)&b[0] = *(const float4*)&Bs[kk][tx * 4];
            *(float4*)&b[4] = *(const float4*)&Bs[kk][64 + tx * 4];
#pragma unroll
            for (int i = 0; i < 8; i++)
#pragma unroll
                for (int j = 0; j < 8; j++)
                    acc[i][j] = fmaf(a[i], b[j], acc[i][j]);
        }
    }
#pragma unroll
    for (int i = 0; i < 8; i++) {
        int row = brow + ((i < 4) ? (ty * 4 + i) : (64 + ty * 4 + (i - 4)));
#pragma unroll
        for (int jq = 0; jq < 2; jq++) {
            int col = bcol + ((jq == 0) ? (tx * 4) : (64 + tx * 4));
            float4 o;
            o.x = acc[i][jq * 4 + 0] + b1[col + 0] + b2[col + 0];
            o.y = acc[i][jq * 4 + 1] + b1[col + 1] + b2[col + 1];
            o.z = acc[i][jq * 4 + 2] + b1[col + 2] + b2[col + 2];
            o.w = acc[i][jq * 4 + 3] + b1[col + 3] + b2[col + 3];
            *(float4*)&C[(size_t)row * N + col] = o;
        }
    }
}

// ---------------- persistent LSTM scan (per-warp early release) --------------------
// grid = 128 CTAs x 256 threads. CTA b owns units [8b, 8b+8); warp w -> unit
// u = 8b + w, rows {u,H+u,2H+u,3H+u} of W_hh in registers (scalar fmaf matvec,
// the twice-proven fast path). Arrival: lane 0 of EACH warp stores its unit's h
// then red.release.gpu cnt[w][t] (+1) — same-thread store->release ordering, no
// CTA bar on the publish path, warp skew absorbed. 8 counters on 8KB-strided
// lines, 128 REDs each. Observe: warp 0 lanes 0-7 acquire-poll one group each.
__global__ void __launch_bounds__(256, 1) lstm_scan_k(
    const float* __restrict__ Whh, const float* __restrict__ gx,
    float* __restrict__ seqout, unsigned* __restrict__ cnt) {
    __shared__ float4 sh[HDIM / 4];
    const int tid  = threadIdx.x;
    const int lane = tid & 31;
    const int w    = tid >> 5;
    const int u    = blockIdx.x * 8 + w;

    // persistent weights in registers (coalesced: lane-stride 16B)
    float4 wr[4][8];
#pragma unroll
    for (int g = 0; g < 4; g++) {
        const float* wp = Whh + (size_t)(g * HDIM + u) * HDIM + lane * 4;
#pragma unroll
        for (int c = 0; c < 8; c++) wr[g][c] = *(const float4*)(wp + c * 128);
    }

    float cst = 0.f;
    const float4* hsrc = 0;

    for (int t = 0; t < SEQ; t++) {
        // gx loads for this step (warp-broadcast, complete under the spin)
        const float* p = gx + (size_t)t * GDIM + u;
        float gi = __ldg(p);
        float gf = __ldg(p + HDIM);
        float gg = __ldg(p + 2 * HDIM);
        float go = __ldg(p + 3 * HDIM);

        if (t == 0) {
            sh[tid] = make_float4(0.f, 0.f, 0.f, 0.f);
            __syncthreads();
        } else {
            // observe step t-1: warp 0 lanes 0-7, one warp-group counter each
            if (w == 0) {
                if (lane < NGRP) {
                    const unsigned* cp = cnt + lane * SEQ + (t - 1);
                    unsigned v;
                    do {
                        asm volatile("ld.acquire.gpu.global.u32 %0, [%1];"
                                     : "=r"(v) : "l"(cp) : "memory");
                    } while (v < (unsigned)NB);
                }
                __syncwarp();
            }
            __syncthreads();                  // propagate observation; also ends
                                              // prior step's sh reads before write
            sh[tid] = __ldcg(hsrc + tid);     // stage h_{t-1} (4KB via L2)
            __syncthreads();
        }

        float a0 = 0.f, a1 = 0.f, a2 = 0.f, a3 = 0.f;
#pragma unroll
        for (int c = 0; c < 8; c++) {
            float4 hv = sh[c * 32 + lane];
            a0 = fmaf(wr[0][c].x, hv.x, a0); a0 = fmaf(wr[0][c].y, hv.y, a0);
            a0 = fmaf(wr[0][c].z, hv.z, a0); a0 = fmaf(wr[0][c].w, hv.w, a0);
            a1 = fmaf(wr[1][c].x, hv.x, a1); a1 = fmaf(wr[1][c].y, hv.y, a1);
            a1 = fmaf(wr[1][c].z, hv.z, a1); a1 = fmaf(wr[1][c].w, hv.w, a1);
            a2 = fmaf(wr[2][c].x, hv.x, a2); a2 = fmaf(wr[2][c].y, hv.y, a2);
            a2 = fmaf(wr[2][c].z, hv.z, a2); a2 = fmaf(wr[2][c].w, hv.w, a2);
            a3 = fmaf(wr[3][c].x, hv.x, a3); a3 = fmaf(wr[3][c].y, hv.y, a3);
            a3 = fmaf(wr[3][c].z, hv.z, a3); a3 = fmaf(wr[3][c].w, hv.w, a3);
        }
#pragma unroll
        for (int s = 16; s > 0; s >>= 1) {
            a0 += __shfl_xor_sync(0xffffffffu, a0, s);
            a1 += __shfl_xor_sync(0xffffffffu, a1, s);
            a2 += __shfl_xor_sync(0xffffffffu, a2, s);
            a3 += __shfl_xor_sync(0xffffffffu, a3, s);
        }
        // all lanes compute identical gates (no divergence, MUFU fast path)
        float iv = fast_sigmoid(a0 + gi);
        float fv = fast_sigmoid(a1 + gf);
        float gv = fast_tanh(a2 + gg);
        float ov = fast_sigmoid(a3 + go);
        cst = fmaf(fv, cst, iv * gv);
        float h = ov * fast_tanh(cst);

        // per-warp publish: store h then release THIS warp's group counter.
        // Same-thread ordering: the release RED makes the h store visible to
        // any consumer that acquires cnt[w][t]. No CTA barrier on this path.
        if (lane == 0) {
            seqout[(size_t)t * HDIM + u] = h;
            asm volatile("red.release.gpu.global.add.u32 [%0], 1;"
                         :: "l"(cnt + w * SEQ + t) : "memory");
        }
        hsrc = (const float4*)(seqout + (size_t)t * HDIM);
        // sh reuse is protected by the two bars at the top of the next step
    }
}

// ---------------- launch ----------------
extern "C" void kernel_launch(void* const* d_in, const int* in_sizes, int n_in,
                              void* d_out, int out_size) {
    const float* x      = (const float*)d_in[0];
    const float* Wih[3] = {(const float*)d_in[1], (const float*)d_in[5],  (const float*)d_in[9]};
    const float* Whh[3] = {(const float*)d_in[2], (const float*)d_in[6],  (const float*)d_in[10]};
    const float* bih[3] = {(const float*)d_in[3], (const float*)d_in[7],  (const float*)d_in[11]};
    const float* bhh[3] = {(const float*)d_in[4], (const float*)d_in[8],  (const float*)d_in[12]};
    const float* fcw    = (const float*)d_in[13];
    const float* fcb    = (const float*)d_in[14];
    float* out = (float*)d_out;

    float *gx, *seqA, *seqB, *Wt, *bz;
    unsigned* cnt;
    cudaGetSymbolAddress((void**)&gx,   g_gx);
    cudaGetSymbolAddress((void**)&seqA, g_seqA);
    cudaGetSymbolAddress((void**)&seqB, g_seqB);
    cudaGetSymbolAddress((void**)&Wt,   g_Wt);
    cudaGetSymbolAddress((void**)&bz,   g_bzero);
    cudaGetSymbolAddress((void**)&cnt,  g_cnt);

    const float* ins[3]  = {x, seqA, seqB};
    float*       outs[3] = {seqA, seqB, seqA};

    dim3 tb(32, 8);
    for (int l = 0; l < 3; l++) {
        transpose_k<<<dim3(HDIM / 32, GDIM / 32), tb>>>(Wih[l], Wt, GDIM, HDIM);
        sgemm_bias_k<<<dim3(GDIM / 128, SEQ / 128), 256>>>(
            ins[l], Wt, bih[l], bhh[l], gx, SEQ, GDIM, HDIM);
        zero_k<<<(NGRP * SEQ + 255) / 256, 256>>>(cnt, NGRP * SEQ);
        lstm_scan_k<<<NB, 256>>>(Whh[l], gx, outs[l], cnt);
    }
    // FC head
    transpose_k<<<dim3(HDIM / 32, NCLS / 32), tb>>>(fcw, Wt, NCLS, HDIM);
    sgemm_bias_k<<<dim3(NCLS / 128, SEQ / 128), 256>>>(
        seqA, Wt, fcb, bz, out, SEQ, NCLS, HDIM);
}